// round 5
// baseline (speedup 1.0000x reference)
#include <cuda_runtime.h>
#include <cstdint>

// DCT per 8x8 patch == out(N,64) = X(N,64) @ (C ⊗ C), separable two-pass
// (1024 FMA/strip), coefficients as FFMA immediates.
// Warp-autonomous cp.async double-buffering: each warp owns a private padded
// 32-strip slice pair and free-runs its own prefetch pipeline (cp.async groups
// are per-thread state). No __syncthreads -> no lockstep memory bursts.

#define THREADS      128
#define WARP_STRIPS  32
#define TILE_STRIPS  128                  // per-CTA grid-stride unit (4 warps x 32)
#define WBUF_F4      (WARP_STRIPS * 17)   // 544 float4 per warp buffer (padded)
#define SMEM_BYTES   (2 * 4 * WBUF_F4 * 16)   // 2 buffers x 4 warps = 69632 B

#define DCT_TABLE(CT)                                                                  \
    const float CT[8][8] = {                                                           \
        {0.353553391f, 0.353553391f, 0.353553391f, 0.353553391f,                       \
         0.353553391f, 0.353553391f, 0.353553391f, 0.353553391f},                      \
        {0.490392640f, 0.415734806f, 0.277785117f, 0.097545161f,                       \
         -0.097545161f, -0.277785117f, -0.415734806f, -0.490392640f},                  \
        {0.461939766f, 0.191341716f, -0.191341716f, -0.461939766f,                     \
         -0.461939766f, -0.191341716f, 0.191341716f, 0.461939766f},                    \
        {0.415734806f, -0.097545161f, -0.490392640f, -0.277785117f,                    \
         0.277785117f, 0.490392640f, 0.097545161f, -0.415734806f},                     \
        {0.353553391f, -0.353553391f, -0.353553391f, 0.353553391f,                     \
         0.353553391f, -0.353553391f, -0.353553391f, 0.353553391f},                    \
        {0.277785117f, -0.490392640f, 0.097545161f, 0.415734806f,                      \
         -0.415734806f, -0.097545161f, 0.490392640f, -0.277785117f},                   \
        {0.191341716f, -0.461939766f, 0.461939766f, -0.191341716f,                     \
         -0.191341716f, 0.461939766f, -0.461939766f, 0.191341716f},                    \
        {0.097545161f, -0.277785117f, 0.415734806f, -0.490392640f,                     \
         0.490392640f, -0.415734806f, 0.277785117f, -0.097545161f}};

__device__ __forceinline__ void cp_async16(float4* smem_dst, const float4* gsrc)
{
    uint32_t s = (uint32_t)__cvta_generic_to_shared(smem_dst);
    asm volatile("cp.async.cg.shared.global [%0], [%1], 16;\n" :: "r"(s), "l"(gsrc));
}
__device__ __forceinline__ void cp_commit() { asm volatile("cp.async.commit_group;\n" ::: "memory"); }
__device__ __forceinline__ void cp_wait1()  { asm volatile("cp.async.wait_group 1;\n" ::: "memory"); }

__global__ __launch_bounds__(THREADS)
void dct_warp_pipe_kernel(const float4* __restrict__ in4, float4* __restrict__ out4,
                          int ntiles)
{
    extern __shared__ float4 sm[];
    const int lane = threadIdx.x & 31;
    const int w    = threadIdx.x >> 5;

    // This warp's two buffers.
    float4* b0 = sm + (2 * w + 0) * WBUF_F4;
    float4* b1 = sm + (2 * w + 1) * WBUF_F4;

    // Coalesced <-> padded mapping for this warp's 32-strip slice:
    // gmem f4 slot (k*32 + lane) -> strip 2k + (lane>>4), chunk lane&15
    // padded smem idx = strip*17 + chunk
    const int cslot = (lane >> 4) * 17 + (lane & 15);   // + 2k*17 per k

    const int stride = gridDim.x;
    int tile = blockIdx.x;

    // gmem base (in float4) of this warp's slice within tile i:
    //   i*TILE_STRIPS*16 + w*WARP_STRIPS*16
    const size_t woff = (size_t)w * (WARP_STRIPS * 16);

    // Prologue: prefetch first tile into b0.
    if (tile < ntiles) {
        const float4* g = in4 + (size_t)tile * (TILE_STRIPS * 16) + woff;
#pragma unroll
        for (int k = 0; k < 16; ++k)
            cp_async16(&b0[2 * k * 17 + cslot], &g[k * 32 + lane]);
    }
    cp_commit();

    int cur = 0;
    for (int i = tile; i < ntiles; i += stride) {
        float4* bc = cur ? b1 : b0;
        float4* bn = cur ? b0 : b1;

        // Prefetch next tile into spare buffer (overlaps this tile's compute).
        int nxt = i + stride;
        if (nxt < ntiles) {
            const float4* g = in4 + (size_t)nxt * (TILE_STRIPS * 16) + woff;
#pragma unroll
            for (int k = 0; k < 16; ++k)
                cp_async16(&bn[2 * k * 17 + cslot], &g[k * 32 + lane]);
        }
        cp_commit();
        cp_wait1();                 // current tile's slice is in smem
        __syncwarp();

        // Own strip (one per lane): smem -> regs, conflict-free (stride-17 pad).
        float x[64];
        float4* sp = bc + lane * 17;
#pragma unroll
        for (int k = 0; k < 16; ++k) {
            float4 v = sp[k];
            x[4 * k + 0] = v.x; x[4 * k + 1] = v.y;
            x[4 * k + 2] = v.z; x[4 * k + 3] = v.w;
        }

        DCT_TABLE(CT);
        // Stage 1 (in place): x[u*8+j] <- sum_v x[u*8+v] * CT[v][j]
#pragma unroll
        for (int u = 0; u < 8; ++u) {
            float tr[8];
#pragma unroll
            for (int j = 0; j < 8; ++j) {
                float a = x[u * 8 + 0] * CT[0][j];
#pragma unroll
                for (int v = 1; v < 8; ++v) a = fmaf(x[u * 8 + v], CT[v][j], a);
                tr[j] = a;
            }
#pragma unroll
            for (int j = 0; j < 8; ++j) x[u * 8 + j] = tr[j];
        }
        // Stage 2: row r streamed straight back to smem (in-place buffer reuse).
#pragma unroll
        for (int r = 0; r < 8; ++r) {
            float o[8];
#pragma unroll
            for (int j = 0; j < 8; ++j) {
                float a = x[0 * 8 + j] * CT[0][r];
#pragma unroll
                for (int u = 1; u < 8; ++u) a = fmaf(x[u * 8 + j], CT[u][r], a);
                o[j] = a;
            }
            sp[2 * r + 0] = make_float4(o[0], o[1], o[2], o[3]);
            sp[2 * r + 1] = make_float4(o[4], o[5], o[6], o[7]);
        }
        __syncwarp();

        // Coalesced smem -> gmem.
        float4* go = out4 + (size_t)i * (TILE_STRIPS * 16) + woff;
#pragma unroll
        for (int k = 0; k < 16; ++k)
            go[k * 32 + lane] = bc[2 * k * 17 + cslot];
        __syncwarp();               // slice free before it becomes a prefetch target

        cur ^= 1;
    }
}

// Tail (strip count not divisible by 128): direct per-thread path, tiny.
__global__ void dct_tail_kernel(const float4* __restrict__ in4,
                                float4* __restrict__ out4,
                                int first_strip, int nstrips)
{
    int strip = first_strip + blockIdx.x * blockDim.x + threadIdx.x;
    if (strip >= nstrips) return;
    float x[64];
    const float4* ip = in4 + (size_t)strip * 16;
#pragma unroll
    for (int k = 0; k < 16; ++k) {
        float4 v = ip[k];
        x[4 * k + 0] = v.x; x[4 * k + 1] = v.y;
        x[4 * k + 2] = v.z; x[4 * k + 3] = v.w;
    }
    DCT_TABLE(CT);
#pragma unroll
    for (int u = 0; u < 8; ++u) {
        float tr[8];
#pragma unroll
        for (int j = 0; j < 8; ++j) {
            float a = x[u * 8 + 0] * CT[0][j];
#pragma unroll
            for (int v = 1; v < 8; ++v) a = fmaf(x[u * 8 + v], CT[v][j], a);
            tr[j] = a;
        }
#pragma unroll
        for (int j = 0; j < 8; ++j) x[u * 8 + j] = tr[j];
    }
    float4* op = out4 + (size_t)strip * 16;
#pragma unroll
    for (int r = 0; r < 8; ++r) {
        float o[8];
#pragma unroll
        for (int j = 0; j < 8; ++j) {
            float a = x[0 * 8 + j] * CT[0][r];
#pragma unroll
            for (int u = 1; u < 8; ++u) a = fmaf(x[u * 8 + j], CT[u][r], a);
            o[j] = a;
        }
        op[2 * r + 0] = make_float4(o[0], o[1], o[2], o[3]);
        op[2 * r + 1] = make_float4(o[4], o[5], o[6], o[7]);
    }
}

extern "C" void kernel_launch(void* const* d_in, const int* in_sizes, int n_in,
                              void* d_out, int out_size)
{
    const float4* in4 = (const float4*)d_in[0];  // (8,3,1024,1024) fp32 contiguous
    float4* out4      = (float4*)d_out;

    int nstrips = in_sizes[0] / 64;              // 393216 on bench shape
    int ntiles  = nstrips / TILE_STRIPS;

    if (ntiles > 0) {
        static int configured = 0;
        if (!configured) {
            cudaFuncSetAttribute(dct_warp_pipe_kernel,
                                 cudaFuncAttributeMaxDynamicSharedMemorySize,
                                 SMEM_BYTES);
            configured = 1;
        }
        int nsm = 148;
        cudaDeviceGetAttribute(&nsm, cudaDevAttrMultiProcessorCount, 0);
        int grid = 3 * nsm;                      // exactly resident: 3 CTAs/SM by smem
        if (grid > ntiles) grid = ntiles;
        dct_warp_pipe_kernel<<<grid, THREADS, SMEM_BYTES>>>(in4, out4, ntiles);
    }
    int rem = nstrips - ntiles * TILE_STRIPS;
    if (rem > 0)
        dct_tail_kernel<<<(rem + 127) / 128, 128>>>(in4, out4,
                                                    ntiles * TILE_STRIPS, nstrips);
}